// round 7
// baseline (speedup 1.0000x reference)
#include <cuda_runtime.h>
#include <cstdint>

#define EPSV 1e-5f
constexpr int BB = 32, CIN = 240, C1 = 24, HH = 56, WWD = 56, HW = 3136;
constexpr int OUP = 240;
constexpr int KSPLIT = 120;

// Scratch — __device__ globals per allocation rules.
__device__ float g_pa[BB * C1 * HW];   // conv1x1 raw partial, k in [0,120)
__device__ float g_pb[BB * C1 * HW];   // conv1x1 raw partial, k in [120,240)
__device__ float g_s2[BB * C1 * HW];   // after dw3x3 + bn2 (== x1)

using u64 = unsigned long long;

__device__ __forceinline__ u64 pk2(float lo, float hi) {
    u64 r; asm("mov.b64 %0, {%1,%2};" : "=l"(r) : "f"(lo), "f"(hi)); return r;
}
__device__ __forceinline__ float2 up2(u64 v) {
    float2 f; asm("mov.b64 {%0,%1}, %2;" : "=f"(f.x), "=f"(f.y) : "l"(v)); return f;
}
__device__ __forceinline__ u64 fma2(u64 a, u64 b, u64 c) {
    u64 d; asm("fma.rn.f32x2 %0, %1, %2, %3;" : "=l"(d) : "l"(a), "l"(b), "l"(c)); return d;
}
__device__ __forceinline__ u64 add2(u64 a, u64 b) {
    u64 d; asm("add.rn.f32x2 %0, %1, %2;" : "=l"(d) : "l"(a), "l"(b)); return d;
}

// ---------------------------------------------------------------------------
// Kernel A: 1x1 conv raw partial sums.
// grid (98 px-tiles, 2 ch-halves, 2 K-halves), 128 thr.
// Thread = 8 pixels x 12 channels: 48 pixel-packed f32x2 accumulators.
// Weights: 6 uniform LDS.128 per k (dual dup-pairs) feeding 48 FFMA2
//   -> 80% of issue slots are FFMA2 (was 44%).
// x: 4x LDG.128 per 2k, depth-2 prefetch (~192 cyc cover; x in L2 for the
//   second ch-half since px-tile is the fastest grid dim).
// ---------------------------------------------------------------------------
__global__ __launch_bounds__(128, 4) void kA(
    const float* __restrict__ x, const float* __restrict__ w) {
    __shared__ ulonglong2 ws2[KSPLIT * 6];   // [k][c2] = {dup w(2c2), dup w(2c2+1)}
    int tid = threadIdx.x;
    int chb = blockIdx.y * 12;               // channel half base
    int kbase = blockIdx.z * KSPLIT;         // K half base
    u64* wsf = reinterpret_cast<u64*>(ws2);
    for (int i = tid; i < KSPLIT * 12; i += 128) {
        int k = i / 12, cc = i % 12;
        float wv = w[(chb + cc) * CIN + kbase + k];
        wsf[i] = pk2(wv, wv);
    }
    __syncthreads();

    // 8 contiguous pixels per thread; HW % 8 == 0 so no batch crossing.
    int p0 = (blockIdx.x * 128 + tid) * 8;
    int b = p0 / HW;
    int s = p0 - b * HW;
    const float* xp = x + (size_t)b * CIN * HW + (size_t)kbase * HW + s;

    u64 acc[12][4];
#pragma unroll
    for (int c = 0; c < 12; c++)
#pragma unroll
        for (int j = 0; j < 4; j++) acc[c][j] = 0ull;

    float4 cur[4], nxt[4];
    cur[0] = *reinterpret_cast<const float4*>(xp);
    cur[1] = *reinterpret_cast<const float4*>(xp + 4);
    cur[2] = *reinterpret_cast<const float4*>(xp + HW);
    cur[3] = *reinterpret_cast<const float4*>(xp + HW + 4);

#pragma unroll 1
    for (int k0 = 0; k0 < KSPLIT; k0 += 2) {
        int kn = (k0 + 2 == KSPLIT) ? 0 : (k0 + 2);   // clamp: redundant L1 hit
        nxt[0] = *reinterpret_cast<const float4*>(xp + (size_t)kn * HW);
        nxt[1] = *reinterpret_cast<const float4*>(xp + (size_t)kn * HW + 4);
        nxt[2] = *reinterpret_cast<const float4*>(xp + (size_t)(kn + 1) * HW);
        nxt[3] = *reinterpret_cast<const float4*>(xp + (size_t)(kn + 1) * HW + 4);
#pragma unroll
        for (int kk = 0; kk < 2; kk++) {
            float4 a = cur[2 * kk], bq = cur[2 * kk + 1];
            u64 x0 = pk2(a.x, a.y);
            u64 x1 = pk2(a.z, a.w);
            u64 x2 = pk2(bq.x, bq.y);
            u64 x3 = pk2(bq.z, bq.w);
            const ulonglong2* wk = ws2 + (k0 + kk) * 6;
#pragma unroll
            for (int c2 = 0; c2 < 6; c2++) {
                ulonglong2 wv = wk[c2];
                acc[2 * c2][0] = fma2(x0, wv.x, acc[2 * c2][0]);
                acc[2 * c2][1] = fma2(x1, wv.x, acc[2 * c2][1]);
                acc[2 * c2][2] = fma2(x2, wv.x, acc[2 * c2][2]);
                acc[2 * c2][3] = fma2(x3, wv.x, acc[2 * c2][3]);
                acc[2 * c2 + 1][0] = fma2(x0, wv.y, acc[2 * c2 + 1][0]);
                acc[2 * c2 + 1][1] = fma2(x1, wv.y, acc[2 * c2 + 1][1]);
                acc[2 * c2 + 1][2] = fma2(x2, wv.y, acc[2 * c2 + 1][2]);
                acc[2 * c2 + 1][3] = fma2(x3, wv.y, acc[2 * c2 + 1][3]);
            }
        }
#pragma unroll
        for (int j = 0; j < 4; j++) cur[j] = nxt[j];
    }
    float* op = (blockIdx.z ? g_pb : g_pa) + ((size_t)b * C1 + chb) * HW + s;
#pragma unroll
    for (int c = 0; c < 12; c++) {
        float2 f0 = up2(acc[c][0]), f1 = up2(acc[c][1]);
        float2 f2 = up2(acc[c][2]), f3 = up2(acc[c][3]);
        *reinterpret_cast<float4*>(op + (size_t)c * HW) =
            make_float4(f0.x, f0.y, f1.x, f1.y);
        *reinterpret_cast<float4*>(op + (size_t)c * HW + 4) =
            make_float4(f2.x, f2.y, f3.x, f3.y);
    }
}

// ---------------------------------------------------------------------------
// Kernel B: merge partials + BN1, depthwise 3x3 + BN2. One q (4px) per thread.
// Flat grid 2352 x 256. Writes g_s2 (for kC, via L2) and out channels [0,24).
// ---------------------------------------------------------------------------
__global__ __launch_bounds__(256) void kB(
    const float* __restrict__ g1, const float* __restrict__ b1,
    const float* __restrict__ m1, const float* __restrict__ v1,
    const float* __restrict__ wdw,
    const float* __restrict__ g2, const float* __restrict__ b2,
    const float* __restrict__ m2, const float* __restrict__ v2,
    float* __restrict__ out) {
    int idx = blockIdx.x * 256 + threadIdx.x;   // 602112 = 32*24*784
    int q = idx % 784;
    int c = (idx / 784) % C1;
    int b = idx / (784 * C1);
    int h = q / 14;
    int w0 = (q % 14) * 4;
    float iv1 = g1[c] * rsqrtf(v1[c] + EPSV);
    float bi1 = b1[c] - m1[c] * iv1;
    size_t poff = ((size_t)b * C1 + c) * HW;
    const float* pa = g_pa + poff;
    const float* pb = g_pb + poff;

    float rb[3][6];
#pragma unroll
    for (int dy = 0; dy < 3; dy++) {
        int hh = h + dy - 1;
        bool hok = (hh >= 0) && (hh < HH);
#pragma unroll
        for (int jx = 0; jx < 6; jx++) {
            int ww = w0 + jx - 1;
            int id2 = hh * WWD + ww;
            rb[dy][jx] = (hok && ww >= 0 && ww < WWD)
                           ? fmaf(pa[id2] + pb[id2], iv1, bi1) : 0.0f;
        }
    }
    float wv[9];
#pragma unroll
    for (int t = 0; t < 9; t++) wv[t] = __ldg(wdw + c * 9 + t);
    float acc[4] = {0.f, 0.f, 0.f, 0.f};
#pragma unroll
    for (int dy = 0; dy < 3; dy++)
#pragma unroll
        for (int dx = 0; dx < 3; dx++) {
            float t = wv[dy * 3 + dx];
#pragma unroll
            for (int j = 0; j < 4; j++) acc[j] = fmaf(rb[dy][dx + j], t, acc[j]);
        }
    float iv2 = g2[c] * rsqrtf(v2[c] + EPSV);
    float bi2 = b2[c] - m2[c] * iv2;
    float4 o = make_float4(fmaf(acc[0], iv2, bi2), fmaf(acc[1], iv2, bi2),
                           fmaf(acc[2], iv2, bi2), fmaf(acc[3], iv2, bi2));
    size_t off = poff + h * WWD + w0;
    *reinterpret_cast<float4*>(g_s2 + off) = o;
    size_t ooff = ((size_t)b * OUP + c) * HW + h * WWD + w0;
    *reinterpret_cast<float4*>(out + ooff) = o;
}

// ---------------------------------------------------------------------------
// Kernel C: adder depthwise (24 -> 216) + BN3 + ReLU into out channels [24,240).
// One q (4px) per thread, grid (7, 24, 32) x 128. Reads g_s2 from L2.
// ---------------------------------------------------------------------------
__global__ __launch_bounds__(128) void kC(
    const float* __restrict__ wadd,
    const float* __restrict__ g3, const float* __restrict__ b3,
    const float* __restrict__ m3, const float* __restrict__ v3,
    float* __restrict__ out) {
    int c = blockIdx.y;
    int b = blockIdx.z;
    __shared__ u64 negtap[81];
    __shared__ float sninv[9], sbias[9];
    int tid = threadIdx.x;
    if (tid < 81) {
        float tv = wadd[c * 81 + tid];
        negtap[tid] = pk2(-tv, -tv);
    }
    if (tid < 9) {
        int ch = c * 9 + tid;
        float iv = g3[ch] * rsqrtf(v3[ch] + EPSV);
        sninv[tid] = -iv;
        sbias[tid] = b3[ch] - m3[ch] * iv;
    }
    __syncthreads();
    int q = blockIdx.x * 128 + tid;
    if (q >= 784) return;
    int h = q / 14;
    int w0 = (q % 14) * 4;
    const float* p = g_s2 + ((size_t)b * C1 + c) * HW;

    float rb[3][6];
#pragma unroll
    for (int dy = 0; dy < 3; dy++) {
        int hh = h + dy - 1;
        bool hok = (hh >= 0) && (hh < HH);
#pragma unroll
        for (int jx = 0; jx < 6; jx++) {
            int ww = w0 + jx - 1;
            rb[dy][jx] = (hok && ww >= 0 && ww < WWD) ? p[hh * WWD + ww] : 0.0f;
        }
    }
    u64 nA[9], nB[9];
#pragma unroll
    for (int dy = 0; dy < 3; dy++)
#pragma unroll
        for (int dx = 0; dx < 3; dx++) {
            nA[dy * 3 + dx] = pk2(rb[dy][dx],     rb[dy][dx + 1]);
            nB[dy * 3 + dx] = pk2(rb[dy][dx + 2], rb[dy][dx + 3]);
        }
    size_t obase = ((size_t)b * OUP + C1 + c * 9) * HW + h * WWD + w0;
#pragma unroll
    for (int r = 0; r < 9; r++) {
        u64 aA = 0ull, aB = 0ull;
#pragma unroll
        for (int t = 0; t < 9; t++) {
            u64 nt = negtap[r * 9 + t];
            u64 dA = add2(nA[t], nt) & 0x7FFFFFFF7FFFFFFFull;
            u64 dB = add2(nB[t], nt) & 0x7FFFFFFF7FFFFFFFull;
            aA = add2(aA, dA);
            aB = add2(aB, dB);
        }
        float2 fa = up2(aA), fb = up2(aB);
        float ni = sninv[r], bi = sbias[r];
        float4 o = make_float4(fmaxf(fmaf(fa.x, ni, bi), 0.f),
                               fmaxf(fmaf(fa.y, ni, bi), 0.f),
                               fmaxf(fmaf(fb.x, ni, bi), 0.f),
                               fmaxf(fmaf(fb.y, ni, bi), 0.f));
        *reinterpret_cast<float4*>(out + obase + (size_t)r * HW) = o;
    }
}

extern "C" void kernel_launch(void* const* d_in, const int* in_sizes, int n_in,
                              void* d_out, int out_size) {
    const float* x   = (const float*)d_in[0];
    const float* wp  = (const float*)d_in[1];
    const float* g1  = (const float*)d_in[2];
    const float* b1  = (const float*)d_in[3];
    const float* m1  = (const float*)d_in[4];
    const float* v1  = (const float*)d_in[5];
    const float* wdw = (const float*)d_in[6];
    const float* g2  = (const float*)d_in[7];
    const float* b2  = (const float*)d_in[8];
    const float* m2  = (const float*)d_in[9];
    const float* v2  = (const float*)d_in[10];
    const float* wa  = (const float*)d_in[11];
    const float* g3  = (const float*)d_in[12];
    const float* b3  = (const float*)d_in[13];
    const float* m3  = (const float*)d_in[14];
    const float* v3  = (const float*)d_in[15];
    float* out = (float*)d_out;

    kA<<<dim3(98, 2, 2), 128>>>(x, wp);
    kB<<<2352, 256>>>(g1, b1, m1, v1, wdw, g2, b2, m2, v2, out);
    kC<<<dim3(7, 24, 32), 128>>>(wa, g3, b3, m3, v3, out);
}

// round 9
// speedup vs baseline: 1.1061x; 1.1061x over previous
#include <cuda_runtime.h>
#include <cstdint>

#define EPSV 1e-5f
constexpr int BB = 32, CIN = 240, C1 = 24, HH = 56, WWD = 56, HW = 3136;
constexpr int OUP = 240;
constexpr int KSPLIT = 120;

// Scratch — __device__ globals per allocation rules.
__device__ float g_pa[BB * C1 * HW];   // conv1x1 raw partial, k in [0,120)
__device__ float g_pb[BB * C1 * HW];   // conv1x1 raw partial, k in [120,240)
__device__ float g_s2[BB * C1 * HW];   // after dw3x3 + bn2 (== x1)

using u64 = unsigned long long;

__device__ __forceinline__ u64 pk2(float lo, float hi) {
    u64 r; asm("mov.b64 %0, {%1,%2};" : "=l"(r) : "f"(lo), "f"(hi)); return r;
}
__device__ __forceinline__ float2 up2(u64 v) {
    float2 f; asm("mov.b64 {%0,%1}, %2;" : "=f"(f.x), "=f"(f.y) : "l"(v)); return f;
}
__device__ __forceinline__ u64 fma2(u64 a, u64 b, u64 c) {
    u64 d; asm("fma.rn.f32x2 %0, %1, %2, %3;" : "=l"(d) : "l"(a), "l"(b), "l"(c)); return d;
}
__device__ __forceinline__ u64 add2(u64 a, u64 b) {
    u64 d; asm("add.rn.f32x2 %0, %1, %2;" : "=l"(d) : "l"(a), "l"(b)); return d;
}

// ---------------------------------------------------------------------------
// Kernel A: 1x1 conv raw partial sums. grid (196 px-tiles, 2 ch-halves,
// 2 K-halves), 128 thr. Thread = 4 pixels x 12 channels (24 f32x2 accs).
// - x loaded as ulonglong2: the two u64 lanes ARE the px-pairs (no pack movs)
// - weights via LDS.128 (2 dup-pairs per load): 6 per k, half the slots
// - prefetch depth 4 k-steps: 4 LDG.128 in flight per warp
// Per 4k: ~130 issue slots, 96 of them FFMA2 -> fma-bound (~17.4us floor).
// ---------------------------------------------------------------------------
__global__ __launch_bounds__(128, 5) void kA(
    const float* __restrict__ x, const float* __restrict__ w) {
    __shared__ ulonglong2 ws2[KSPLIT * 6];   // [k][c2] = 2 dup weight pairs
    int tid = threadIdx.x;
    int chb = blockIdx.y * 12;               // channel half base
    int kbase = blockIdx.z * KSPLIT;         // K half base
    u64* wsf = reinterpret_cast<u64*>(ws2);
    for (int i = tid; i < KSPLIT * 12; i += 128) {
        int k = i / 12, cc = i % 12;
        float wv = w[(chb + cc) * CIN + kbase + k];
        wsf[i] = pk2(wv, wv);
    }
    __syncthreads();

    int p0 = (blockIdx.x * 128 + tid) * 4;   // 4 contiguous px, HW%4==0
    int b = p0 / HW;
    int s = p0 - b * HW;
    const float* xpf = x + (size_t)b * CIN * HW + (size_t)kbase * HW + s;

    u64 acc[12][2];
#pragma unroll
    for (int c = 0; c < 12; c++) { acc[c][0] = 0ull; acc[c][1] = 0ull; }

    ulonglong2 cur[4], nxt[4];
#pragma unroll
    for (int j = 0; j < 4; j++)
        cur[j] = *reinterpret_cast<const ulonglong2*>(xpf + (size_t)j * HW);

#pragma unroll 1
    for (int k0 = 0; k0 < KSPLIT; k0 += 4) {
        int kn = (k0 + 4 < KSPLIT) ? (k0 + 4) : 0;   // clamp: redundant L1 hit
#pragma unroll
        for (int j = 0; j < 4; j++)
            nxt[j] = *reinterpret_cast<const ulonglong2*>(xpf + (size_t)(kn + j) * HW);
#pragma unroll
        for (int kk = 0; kk < 4; kk++) {
            u64 x0 = cur[kk].x;      // px 0,1
            u64 x1 = cur[kk].y;      // px 2,3
            const ulonglong2* wk = ws2 + (k0 + kk) * 6;
#pragma unroll
            for (int c2 = 0; c2 < 6; c2++) {
                ulonglong2 wv = wk[c2];
                acc[2 * c2][0]     = fma2(x0, wv.x, acc[2 * c2][0]);
                acc[2 * c2][1]     = fma2(x1, wv.x, acc[2 * c2][1]);
                acc[2 * c2 + 1][0] = fma2(x0, wv.y, acc[2 * c2 + 1][0]);
                acc[2 * c2 + 1][1] = fma2(x1, wv.y, acc[2 * c2 + 1][1]);
            }
        }
#pragma unroll
        for (int j = 0; j < 4; j++) cur[j] = nxt[j];
    }
    float* op = (blockIdx.z ? g_pb : g_pa) + ((size_t)b * C1 + chb) * HW + s;
#pragma unroll
    for (int c = 0; c < 12; c++) {
        float2 f0 = up2(acc[c][0]), f1 = up2(acc[c][1]);
        *reinterpret_cast<float4*>(op + (size_t)c * HW) =
            make_float4(f0.x, f0.y, f1.x, f1.y);
    }
}

// ---------------------------------------------------------------------------
// Kernel B: merge partials + BN1, depthwise 3x3 + BN2. One q (4px) per thread.
// Flat grid 2352 x 256. Writes g_s2 (for kC, via L2) and out channels [0,24).
// ---------------------------------------------------------------------------
__global__ __launch_bounds__(256) void kB(
    const float* __restrict__ g1, const float* __restrict__ b1,
    const float* __restrict__ m1, const float* __restrict__ v1,
    const float* __restrict__ wdw,
    const float* __restrict__ g2, const float* __restrict__ b2,
    const float* __restrict__ m2, const float* __restrict__ v2,
    float* __restrict__ out) {
    int idx = blockIdx.x * 256 + threadIdx.x;   // 602112 = 32*24*784
    int q = idx % 784;
    int c = (idx / 784) % C1;
    int b = idx / (784 * C1);
    int h = q / 14;
    int w0 = (q % 14) * 4;
    float iv1 = g1[c] * rsqrtf(v1[c] + EPSV);
    float bi1 = b1[c] - m1[c] * iv1;
    size_t poff = ((size_t)b * C1 + c) * HW;
    const float* pa = g_pa + poff;
    const float* pb = g_pb + poff;

    float rb[3][6];
#pragma unroll
    for (int dy = 0; dy < 3; dy++) {
        int hh = h + dy - 1;
        bool hok = (hh >= 0) && (hh < HH);
#pragma unroll
        for (int jx = 0; jx < 6; jx++) {
            int ww = w0 + jx - 1;
            int id2 = hh * WWD + ww;
            rb[dy][jx] = (hok && ww >= 0 && ww < WWD)
                           ? fmaf(pa[id2] + pb[id2], iv1, bi1) : 0.0f;
        }
    }
    float wv[9];
#pragma unroll
    for (int t = 0; t < 9; t++) wv[t] = __ldg(wdw + c * 9 + t);
    float acc[4] = {0.f, 0.f, 0.f, 0.f};
#pragma unroll
    for (int dy = 0; dy < 3; dy++)
#pragma unroll
        for (int dx = 0; dx < 3; dx++) {
            float t = wv[dy * 3 + dx];
#pragma unroll
            for (int j = 0; j < 4; j++) acc[j] = fmaf(rb[dy][dx + j], t, acc[j]);
        }
    float iv2 = g2[c] * rsqrtf(v2[c] + EPSV);
    float bi2 = b2[c] - m2[c] * iv2;
    float4 o = make_float4(fmaf(acc[0], iv2, bi2), fmaf(acc[1], iv2, bi2),
                           fmaf(acc[2], iv2, bi2), fmaf(acc[3], iv2, bi2));
    size_t off = poff + h * WWD + w0;
    *reinterpret_cast<float4*>(g_s2 + off) = o;
    size_t ooff = ((size_t)b * OUP + c) * HW + h * WWD + w0;
    *reinterpret_cast<float4*>(out + ooff) = o;
}

// ---------------------------------------------------------------------------
// Kernel C: adder depthwise (24 -> 216) + BN3 + ReLU into out channels [24,240).
// One q (4px) per thread, grid (7, 24, 32) x 128. Reads g_s2 from L2.
// ---------------------------------------------------------------------------
__global__ __launch_bounds__(128) void kC(
    const float* __restrict__ wadd,
    const float* __restrict__ g3, const float* __restrict__ b3,
    const float* __restrict__ m3, const float* __restrict__ v3,
    float* __restrict__ out) {
    int c = blockIdx.y;
    int b = blockIdx.z;
    __shared__ u64 negtap[81];
    __shared__ float sninv[9], sbias[9];
    int tid = threadIdx.x;
    if (tid < 81) {
        float tv = wadd[c * 81 + tid];
        negtap[tid] = pk2(-tv, -tv);
    }
    if (tid < 9) {
        int ch = c * 9 + tid;
        float iv = g3[ch] * rsqrtf(v3[ch] + EPSV);
        sninv[tid] = -iv;
        sbias[tid] = b3[ch] - m3[ch] * iv;
    }
    __syncthreads();
    int q = blockIdx.x * 128 + tid;
    if (q >= 784) return;
    int h = q / 14;
    int w0 = (q % 14) * 4;
    const float* p = g_s2 + ((size_t)b * C1 + c) * HW;

    float rb[3][6];
#pragma unroll
    for (int dy = 0; dy < 3; dy++) {
        int hh = h + dy - 1;
        bool hok = (hh >= 0) && (hh < HH);
#pragma unroll
        for (int jx = 0; jx < 6; jx++) {
            int ww = w0 + jx - 1;
            rb[dy][jx] = (hok && ww >= 0 && ww < WWD) ? p[hh * WWD + ww] : 0.0f;
        }
    }
    u64 nA[9], nB[9];
#pragma unroll
    for (int dy = 0; dy < 3; dy++)
#pragma unroll
        for (int dx = 0; dx < 3; dx++) {
            nA[dy * 3 + dx] = pk2(rb[dy][dx],     rb[dy][dx + 1]);
            nB[dy * 3 + dx] = pk2(rb[dy][dx + 2], rb[dy][dx + 3]);
        }
    size_t obase = ((size_t)b * OUP + C1 + c * 9) * HW + h * WWD + w0;
#pragma unroll
    for (int r = 0; r < 9; r++) {
        u64 aA = 0ull, aB = 0ull;
#pragma unroll
        for (int t = 0; t < 9; t++) {
            u64 nt = negtap[r * 9 + t];
            u64 dA = add2(nA[t], nt) & 0x7FFFFFFF7FFFFFFFull;
            u64 dB = add2(nB[t], nt) & 0x7FFFFFFF7FFFFFFFull;
            aA = add2(aA, dA);
            aB = add2(aB, dB);
        }
        float2 fa = up2(aA), fb = up2(aB);
        float ni = sninv[r], bi = sbias[r];
        float4 o = make_float4(fmaxf(fmaf(fa.x, ni, bi), 0.f),
                               fmaxf(fmaf(fa.y, ni, bi), 0.f),
                               fmaxf(fmaf(fb.x, ni, bi), 0.f),
                               fmaxf(fmaf(fb.y, ni, bi), 0.f));
        *reinterpret_cast<float4*>(out + obase + (size_t)r * HW) = o;
    }
}

extern "C" void kernel_launch(void* const* d_in, const int* in_sizes, int n_in,
                              void* d_out, int out_size) {
    const float* x   = (const float*)d_in[0];
    const float* wp  = (const float*)d_in[1];
    const float* g1  = (const float*)d_in[2];
    const float* b1  = (const float*)d_in[3];
    const float* m1  = (const float*)d_in[4];
    const float* v1  = (const float*)d_in[5];
    const float* wdw = (const float*)d_in[6];
    const float* g2  = (const float*)d_in[7];
    const float* b2  = (const float*)d_in[8];
    const float* m2  = (const float*)d_in[9];
    const float* v2  = (const float*)d_in[10];
    const float* wa  = (const float*)d_in[11];
    const float* g3  = (const float*)d_in[12];
    const float* b3  = (const float*)d_in[13];
    const float* m3  = (const float*)d_in[14];
    const float* v3  = (const float*)d_in[15];
    float* out = (float*)d_out;

    kA<<<dim3(196, 2, 2), 128>>>(x, wp);
    kB<<<2352, 256>>>(g1, b1, m1, v1, wdw, g2, b2, m2, v2, out);
    kC<<<dim3(7, 24, 32), 128>>>(wa, g3, b3, m3, v3, out);
}

// round 10
// speedup vs baseline: 1.2208x; 1.1037x over previous
#include <cuda_runtime.h>
#include <cstdint>

#define EPSV 1e-5f
constexpr int BB = 32, CIN = 240, C1 = 24, HH = 56, WWD = 56, HW = 3136;
constexpr int OUP = 240;
constexpr int KSPLIT = 120;

// Scratch — __device__ globals per allocation rules.
__device__ float g_pa[BB * C1 * HW];   // conv1x1 raw partial, k in [0,120)
__device__ float g_pb[BB * C1 * HW];   // conv1x1 raw partial, k in [120,240)
__device__ float g_s2[BB * C1 * HW];   // after dw3x3 + bn2 (== x1)

using u64 = unsigned long long;

__device__ __forceinline__ u64 pk2(float lo, float hi) {
    u64 r; asm("mov.b64 %0, {%1,%2};" : "=l"(r) : "f"(lo), "f"(hi)); return r;
}
__device__ __forceinline__ float2 up2(u64 v) {
    float2 f; asm("mov.b64 {%0,%1}, %2;" : "=f"(f.x), "=f"(f.y) : "l"(v)); return f;
}
__device__ __forceinline__ u64 fma2(u64 a, u64 b, u64 c) {
    u64 d; asm("fma.rn.f32x2 %0, %1, %2, %3;" : "=l"(d) : "l"(a), "l"(b), "l"(c)); return d;
}
__device__ __forceinline__ u64 add2(u64 a, u64 b) {
    u64 d; asm("add.rn.f32x2 %0, %1, %2;" : "=l"(d) : "l"(a), "l"(b)); return d;
}

// ---------------------------------------------------------------------------
// Kernel A: 1x1 conv raw partial sums. grid (196 px-tiles, 2 ch-halves,
// 2 K-halves), 128 thr. Thread = 4 pixels x 12 channels (24 f32x2 accs).
// R6 dataflow + two fixes:
//  - x loaded as ulonglong2 (u64 lanes ARE px-pairs; no pack movs)
//  - ping-pong A/B buffers, 8k loop body: no cur=nxt copy movs, ~4k prefetch
// Weights stay LDS.64 dup-pair broadcasts (1 wavefront each — R9's LDS.128
// doubled L1 traffic and regressed).
// ---------------------------------------------------------------------------
__global__ __launch_bounds__(128, 5) void kA(
    const float* __restrict__ x, const float* __restrict__ w) {
    __shared__ u64 ws[KSPLIT * 12];          // [k][c] = {w,w} dup pairs
    int tid = threadIdx.x;
    int chb = blockIdx.y * 12;               // channel half base
    int kbase = blockIdx.z * KSPLIT;         // K half base
    for (int i = tid; i < KSPLIT * 12; i += 128) {
        int k = i / 12, cc = i % 12;
        float wv = w[(chb + cc) * CIN + kbase + k];
        ws[i] = pk2(wv, wv);
    }
    __syncthreads();

    int p0 = (blockIdx.x * 128 + tid) * 4;   // 4 contiguous px, HW%4==0
    int b = p0 / HW;
    int s = p0 - b * HW;
    const float* xpf = x + (size_t)b * CIN * HW + (size_t)kbase * HW + s;

    u64 acc[12][2];
#pragma unroll
    for (int c = 0; c < 12; c++) { acc[c][0] = 0ull; acc[c][1] = 0ull; }

    ulonglong2 bufA[4], bufB[4];
#pragma unroll
    for (int j = 0; j < 4; j++) {
        bufA[j] = *reinterpret_cast<const ulonglong2*>(xpf + (size_t)j * HW);
        bufB[j] = *reinterpret_cast<const ulonglong2*>(xpf + (size_t)(4 + j) * HW);
    }

#pragma unroll 1
    for (int k0 = 0; k0 < KSPLIT; k0 += 8) {
        // compute A-half (k0..k0+3)
#pragma unroll
        for (int kk = 0; kk < 4; kk++) {
            u64 x0 = bufA[kk].x, x1 = bufA[kk].y;
            const u64* wk = ws + (k0 + kk) * 12;
#pragma unroll
            for (int c = 0; c < 12; c++) {
                u64 wv = wk[c];
                acc[c][0] = fma2(x0, wv, acc[c][0]);
                acc[c][1] = fma2(x1, wv, acc[c][1]);
            }
        }
        // refill A for k0+8 (clamp: harmless L1 re-hit on last iter)
        {
            int ka = (k0 + 8 < KSPLIT) ? (k0 + 8) : 0;
#pragma unroll
            for (int j = 0; j < 4; j++)
                bufA[j] = *reinterpret_cast<const ulonglong2*>(
                    xpf + (size_t)(ka + j) * HW);
        }
        // compute B-half (k0+4..k0+7)
#pragma unroll
        for (int kk = 0; kk < 4; kk++) {
            u64 x0 = bufB[kk].x, x1 = bufB[kk].y;
            const u64* wk = ws + (k0 + 4 + kk) * 12;
#pragma unroll
            for (int c = 0; c < 12; c++) {
                u64 wv = wk[c];
                acc[c][0] = fma2(x0, wv, acc[c][0]);
                acc[c][1] = fma2(x1, wv, acc[c][1]);
            }
        }
        // refill B for k0+12
        {
            int kb2 = (k0 + 12 < KSPLIT) ? (k0 + 12) : 0;
#pragma unroll
            for (int j = 0; j < 4; j++)
                bufB[j] = *reinterpret_cast<const ulonglong2*>(
                    xpf + (size_t)(kb2 + j) * HW);
        }
    }
    float* op = (blockIdx.z ? g_pb : g_pa) + ((size_t)b * C1 + chb) * HW + s;
#pragma unroll
    for (int c = 0; c < 12; c++) {
        float2 f0 = up2(acc[c][0]), f1 = up2(acc[c][1]);
        *reinterpret_cast<float4*>(op + (size_t)c * HW) =
            make_float4(f0.x, f0.y, f1.x, f1.y);
    }
}

// ---------------------------------------------------------------------------
// Kernel B: merge partials + BN1, depthwise 3x3 + BN2. One q (4px) per thread.
// Flat grid 2352 x 256. Writes g_s2 (for kC, via L2) and out channels [0,24).
// ---------------------------------------------------------------------------
__global__ __launch_bounds__(256) void kB(
    const float* __restrict__ g1, const float* __restrict__ b1,
    const float* __restrict__ m1, const float* __restrict__ v1,
    const float* __restrict__ wdw,
    const float* __restrict__ g2, const float* __restrict__ b2,
    const float* __restrict__ m2, const float* __restrict__ v2,
    float* __restrict__ out) {
    int idx = blockIdx.x * 256 + threadIdx.x;   // 602112 = 32*24*784
    int q = idx % 784;
    int c = (idx / 784) % C1;
    int b = idx / (784 * C1);
    int h = q / 14;
    int w0 = (q % 14) * 4;
    float iv1 = g1[c] * rsqrtf(v1[c] + EPSV);
    float bi1 = b1[c] - m1[c] * iv1;
    size_t poff = ((size_t)b * C1 + c) * HW;
    const float* pa = g_pa + poff;
    const float* pb = g_pb + poff;

    float rb[3][6];
#pragma unroll
    for (int dy = 0; dy < 3; dy++) {
        int hh = h + dy - 1;
        bool hok = (hh >= 0) && (hh < HH);
#pragma unroll
        for (int jx = 0; jx < 6; jx++) {
            int ww = w0 + jx - 1;
            int id2 = hh * WWD + ww;
            rb[dy][jx] = (hok && ww >= 0 && ww < WWD)
                           ? fmaf(pa[id2] + pb[id2], iv1, bi1) : 0.0f;
        }
    }
    float wv[9];
#pragma unroll
    for (int t = 0; t < 9; t++) wv[t] = __ldg(wdw + c * 9 + t);
    float acc[4] = {0.f, 0.f, 0.f, 0.f};
#pragma unroll
    for (int dy = 0; dy < 3; dy++)
#pragma unroll
        for (int dx = 0; dx < 3; dx++) {
            float t = wv[dy * 3 + dx];
#pragma unroll
            for (int j = 0; j < 4; j++) acc[j] = fmaf(rb[dy][dx + j], t, acc[j]);
        }
    float iv2 = g2[c] * rsqrtf(v2[c] + EPSV);
    float bi2 = b2[c] - m2[c] * iv2;
    float4 o = make_float4(fmaf(acc[0], iv2, bi2), fmaf(acc[1], iv2, bi2),
                           fmaf(acc[2], iv2, bi2), fmaf(acc[3], iv2, bi2));
    size_t off = poff + h * WWD + w0;
    *reinterpret_cast<float4*>(g_s2 + off) = o;
    size_t ooff = ((size_t)b * OUP + c) * HW + h * WWD + w0;
    *reinterpret_cast<float4*>(out + ooff) = o;
}

// ---------------------------------------------------------------------------
// Kernel C: adder depthwise (24 -> 216) + BN3 + ReLU into out channels [24,240).
// One q (4px) per thread, grid (7, 24, 32) x 128. Reads g_s2 from L2.
// ---------------------------------------------------------------------------
__global__ __launch_bounds__(128) void kC(
    const float* __restrict__ wadd,
    const float* __restrict__ g3, const float* __restrict__ b3,
    const float* __restrict__ m3, const float* __restrict__ v3,
    float* __restrict__ out) {
    int c = blockIdx.y;
    int b = blockIdx.z;
    __shared__ u64 negtap[81];
    __shared__ float sninv[9], sbias[9];
    int tid = threadIdx.x;
    if (tid < 81) {
        float tv = wadd[c * 81 + tid];
        negtap[tid] = pk2(-tv, -tv);
    }
    if (tid < 9) {
        int ch = c * 9 + tid;
        float iv = g3[ch] * rsqrtf(v3[ch] + EPSV);
        sninv[tid] = -iv;
        sbias[tid] = b3[ch] - m3[ch] * iv;
    }
    __syncthreads();
    int q = blockIdx.x * 128 + tid;
    if (q >= 784) return;
    int h = q / 14;
    int w0 = (q % 14) * 4;
    const float* p = g_s2 + ((size_t)b * C1 + c) * HW;

    float rb[3][6];
#pragma unroll
    for (int dy = 0; dy < 3; dy++) {
        int hh = h + dy - 1;
        bool hok = (hh >= 0) && (hh < HH);
#pragma unroll
        for (int jx = 0; jx < 6; jx++) {
            int ww = w0 + jx - 1;
            rb[dy][jx] = (hok && ww >= 0 && ww < WWD) ? p[hh * WWD + ww] : 0.0f;
        }
    }
    u64 nA[9], nB[9];
#pragma unroll
    for (int dy = 0; dy < 3; dy++)
#pragma unroll
        for (int dx = 0; dx < 3; dx++) {
            nA[dy * 3 + dx] = pk2(rb[dy][dx],     rb[dy][dx + 1]);
            nB[dy * 3 + dx] = pk2(rb[dy][dx + 2], rb[dy][dx + 3]);
        }
    size_t obase = ((size_t)b * OUP + C1 + c * 9) * HW + h * WWD + w0;
#pragma unroll
    for (int r = 0; r < 9; r++) {
        u64 aA = 0ull, aB = 0ull;
#pragma unroll
        for (int t = 0; t < 9; t++) {
            u64 nt = negtap[r * 9 + t];
            u64 dA = add2(nA[t], nt) & 0x7FFFFFFF7FFFFFFFull;
            u64 dB = add2(nB[t], nt) & 0x7FFFFFFF7FFFFFFFull;
            aA = add2(aA, dA);
            aB = add2(aB, dB);
        }
        float2 fa = up2(aA), fb = up2(aB);
        float ni = sninv[r], bi = sbias[r];
        float4 o = make_float4(fmaxf(fmaf(fa.x, ni, bi), 0.f),
                               fmaxf(fmaf(fa.y, ni, bi), 0.f),
                               fmaxf(fmaf(fb.x, ni, bi), 0.f),
                               fmaxf(fmaf(fb.y, ni, bi), 0.f));
        *reinterpret_cast<float4*>(out + obase + (size_t)r * HW) = o;
    }
}

extern "C" void kernel_launch(void* const* d_in, const int* in_sizes, int n_in,
                              void* d_out, int out_size) {
    const float* x   = (const float*)d_in[0];
    const float* wp  = (const float*)d_in[1];
    const float* g1  = (const float*)d_in[2];
    const float* b1  = (const float*)d_in[3];
    const float* m1  = (const float*)d_in[4];
    const float* v1  = (const float*)d_in[5];
    const float* wdw = (const float*)d_in[6];
    const float* g2  = (const float*)d_in[7];
    const float* b2  = (const float*)d_in[8];
    const float* m2  = (const float*)d_in[9];
    const float* v2  = (const float*)d_in[10];
    const float* wa  = (const float*)d_in[11];
    const float* g3  = (const float*)d_in[12];
    const float* b3  = (const float*)d_in[13];
    const float* m3  = (const float*)d_in[14];
    const float* v3  = (const float*)d_in[15];
    float* out = (float*)d_out;

    kA<<<dim3(196, 2, 2), 128>>>(x, wp);
    kB<<<2352, 256>>>(g1, b1, m1, v1, wdw, g2, b2, m2, v2, out);
    kC<<<dim3(7, 24, 32), 128>>>(wa, g3, b3, m3, v3, out);
}